// round 2
// baseline (speedup 1.0000x reference)
#include <cuda_runtime.h>

#define NN 50000
#define TT 10
#define EE 1000000
#define HH 8

// ---------------- device scratch (no allocations allowed) ----------------
__device__ float g_hidden[NN * HH];   // [N,H] hidden state
__device__ float g_s[NN];             // per-node sigmoid(message MLP) for current frame
__device__ float g_agg[NN];           // per-node aggregated messages
__device__ float g_eaT[TT * EE];      // edge_attr transposed to [T,E]

// ---------------- weights in shared memory ----------------
struct __align__(16) Weights {
    float m1w1[9 * 32];
    float m1b1[32];
    float m1w2[32 * 32];
    float m1b2[32];
    float m1w3[32];
    float m1b3;
    float pad[3];
    float m2w1[10 * 32];
    float m2b1[32];
    float m2w2[32 * 8];
    float m2b2[8];
    float ow1[8 * 16];
    float ob1[16];
    float ow2[16];
    float ob2;
};

struct WPtrs {
    const float *m1w1, *m1b1, *m1w2, *m1b2, *m1w3, *m1b3;
    const float *m2w1, *m2b1, *m2w2, *m2b2;
    const float *ow1, *ob1, *ow2, *ob2;
};

__device__ __forceinline__ void load_weights(Weights* W, const WPtrs p) {
    const int tid = threadIdx.x, nt = blockDim.x;
    for (int i = tid; i < 9 * 32; i += nt)  W->m1w1[i] = p.m1w1[i];
    for (int i = tid; i < 32; i += nt)      W->m1b1[i] = p.m1b1[i];
    for (int i = tid; i < 32 * 32; i += nt) W->m1w2[i] = p.m1w2[i];
    for (int i = tid; i < 32; i += nt)      W->m1b2[i] = p.m1b2[i];
    for (int i = tid; i < 32; i += nt)      W->m1w3[i] = p.m1w3[i];
    for (int i = tid; i < 10 * 32; i += nt) W->m2w1[i] = p.m2w1[i];
    for (int i = tid; i < 32; i += nt)      W->m2b1[i] = p.m2b1[i];
    for (int i = tid; i < 32 * 8; i += nt)  W->m2w2[i] = p.m2w2[i];
    for (int i = tid; i < 8; i += nt)       W->m2b2[i] = p.m2b2[i];
    for (int i = tid; i < 8 * 16; i += nt)  W->ow1[i] = p.ow1[i];
    for (int i = tid; i < 16; i += nt)      W->ob1[i] = p.ob1[i];
    for (int i = tid; i < 16; i += nt)      W->ow2[i] = p.ow2[i];
    if (tid == 0) { W->m1b3 = p.m1b3[0]; W->ob2 = p.ob2[0]; }
}

__device__ __forceinline__ float fast_sigmoid(float z) {
    return 1.0f / (1.0f + __expf(-z));
}

// Message MLP on per-node features [x0, hidden(8)] -> sigmoid scalar.
// (Edge-independent: the reference's edge MLP only reads source-node features.)
__device__ __forceinline__ float mlp1(const Weights* W, float x0, const float h[HH]) {
    float a[32];
    {
        const float4* wv = (const float4*)W->m1w1;
        const float4* bv = (const float4*)W->m1b1;
        #pragma unroll
        for (int j4 = 0; j4 < 8; j4++) {
            float4 w = wv[j4]; float4 b = bv[j4];
            a[4 * j4 + 0] = fmaf(x0, w.x, b.x);
            a[4 * j4 + 1] = fmaf(x0, w.y, b.y);
            a[4 * j4 + 2] = fmaf(x0, w.z, b.z);
            a[4 * j4 + 3] = fmaf(x0, w.w, b.w);
        }
    }
    #pragma unroll
    for (int i = 0; i < HH; i++) {
        float hi = h[i];
        const float4* wr = (const float4*)(W->m1w1 + (i + 1) * 32);
        #pragma unroll
        for (int j4 = 0; j4 < 8; j4++) {
            float4 w = wr[j4];
            a[4 * j4 + 0] = fmaf(hi, w.x, a[4 * j4 + 0]);
            a[4 * j4 + 1] = fmaf(hi, w.y, a[4 * j4 + 1]);
            a[4 * j4 + 2] = fmaf(hi, w.z, a[4 * j4 + 2]);
            a[4 * j4 + 3] = fmaf(hi, w.w, a[4 * j4 + 3]);
        }
    }
    #pragma unroll
    for (int j = 0; j < 32; j++) a[j] = fmaxf(a[j], 0.0f);

    float b[32];
    {
        const float4* bv = (const float4*)W->m1b2;
        #pragma unroll
        for (int j4 = 0; j4 < 8; j4++) {
            float4 bb = bv[j4];
            b[4 * j4 + 0] = bb.x; b[4 * j4 + 1] = bb.y;
            b[4 * j4 + 2] = bb.z; b[4 * j4 + 3] = bb.w;
        }
    }
    #pragma unroll
    for (int i = 0; i < 32; i++) {
        float ai = a[i];
        const float4* wr = (const float4*)(W->m1w2 + i * 32);
        #pragma unroll
        for (int j4 = 0; j4 < 8; j4++) {
            float4 w = wr[j4];
            b[4 * j4 + 0] = fmaf(ai, w.x, b[4 * j4 + 0]);
            b[4 * j4 + 1] = fmaf(ai, w.y, b[4 * j4 + 1]);
            b[4 * j4 + 2] = fmaf(ai, w.z, b[4 * j4 + 2]);
            b[4 * j4 + 3] = fmaf(ai, w.w, b[4 * j4 + 3]);
        }
    }
    float z = W->m1b3;
    {
        const float4* wv = (const float4*)W->m1w3;
        #pragma unroll
        for (int i4 = 0; i4 < 8; i4++) {
            float4 w = wv[i4];
            z = fmaf(fmaxf(b[4 * i4 + 0], 0.0f), w.x, z);
            z = fmaf(fmaxf(b[4 * i4 + 1], 0.0f), w.y, z);
            z = fmaf(fmaxf(b[4 * i4 + 2], 0.0f), w.z, z);
            z = fmaf(fmaxf(b[4 * i4 + 3], 0.0f), w.w, z);
        }
    }
    return fast_sigmoid(z);
}

// Update MLP: [x1, hidden(8), agg] (10) -> 32 -> relu -> 8 -> relu -> tanh
__device__ __forceinline__ void mlp2(const Weights* W, const float upd[10], float hnew[HH]) {
    float a[32];
    {
        const float4* bv = (const float4*)W->m2b1;
        #pragma unroll
        for (int j4 = 0; j4 < 8; j4++) {
            float4 bb = bv[j4];
            a[4 * j4 + 0] = bb.x; a[4 * j4 + 1] = bb.y;
            a[4 * j4 + 2] = bb.z; a[4 * j4 + 3] = bb.w;
        }
    }
    #pragma unroll
    for (int i = 0; i < 10; i++) {
        float ui = upd[i];
        const float4* wr = (const float4*)(W->m2w1 + i * 32);
        #pragma unroll
        for (int j4 = 0; j4 < 8; j4++) {
            float4 w = wr[j4];
            a[4 * j4 + 0] = fmaf(ui, w.x, a[4 * j4 + 0]);
            a[4 * j4 + 1] = fmaf(ui, w.y, a[4 * j4 + 1]);
            a[4 * j4 + 2] = fmaf(ui, w.z, a[4 * j4 + 2]);
            a[4 * j4 + 3] = fmaf(ui, w.w, a[4 * j4 + 3]);
        }
    }
    #pragma unroll
    for (int j = 0; j < 32; j++) a[j] = fmaxf(a[j], 0.0f);

    float b[HH];
    {
        const float4* bv = (const float4*)W->m2b2;
        float4 b0 = bv[0], b1 = bv[1];
        b[0] = b0.x; b[1] = b0.y; b[2] = b0.z; b[3] = b0.w;
        b[4] = b1.x; b[5] = b1.y; b[6] = b1.z; b[7] = b1.w;
    }
    #pragma unroll
    for (int i = 0; i < 32; i++) {
        float ai = a[i];
        const float4* wr = (const float4*)(W->m2w2 + i * 8);
        float4 w0 = wr[0], w1 = wr[1];
        b[0] = fmaf(ai, w0.x, b[0]); b[1] = fmaf(ai, w0.y, b[1]);
        b[2] = fmaf(ai, w0.z, b[2]); b[3] = fmaf(ai, w0.w, b[3]);
        b[4] = fmaf(ai, w1.x, b[4]); b[5] = fmaf(ai, w1.y, b[5]);
        b[6] = fmaf(ai, w1.z, b[6]); b[7] = fmaf(ai, w1.w, b[7]);
    }
    // Reference: hidden_new = tanh(relu(z2))  -- the ReLU was the round-1 bug.
    #pragma unroll
    for (int j = 0; j < HH; j++) hnew[j] = tanhf(fmaxf(b[j], 0.0f));
}

// Readout: hidden(8) -> 16 -> sigmoid scalar
__device__ __forceinline__ float node_out(const Weights* W, const float hnew[HH]) {
    float o[16];
    {
        const float4* bv = (const float4*)W->ob1;
        #pragma unroll
        for (int j4 = 0; j4 < 4; j4++) {
            float4 bb = bv[j4];
            o[4 * j4 + 0] = bb.x; o[4 * j4 + 1] = bb.y;
            o[4 * j4 + 2] = bb.z; o[4 * j4 + 3] = bb.w;
        }
    }
    #pragma unroll
    for (int i = 0; i < HH; i++) {
        float hi = hnew[i];
        const float4* wr = (const float4*)(W->ow1 + i * 16);
        #pragma unroll
        for (int j4 = 0; j4 < 4; j4++) {
            float4 w = wr[j4];
            o[4 * j4 + 0] = fmaf(hi, w.x, o[4 * j4 + 0]);
            o[4 * j4 + 1] = fmaf(hi, w.y, o[4 * j4 + 1]);
            o[4 * j4 + 2] = fmaf(hi, w.z, o[4 * j4 + 2]);
            o[4 * j4 + 3] = fmaf(hi, w.w, o[4 * j4 + 3]);
        }
    }
    float z = W->ob2;
    {
        const float4* wv = (const float4*)W->ow2;
        #pragma unroll
        for (int i4 = 0; i4 < 4; i4++) {
            float4 w = wv[i4];
            z = fmaf(fmaxf(o[4 * i4 + 0], 0.0f), w.x, z);
            z = fmaf(fmaxf(o[4 * i4 + 1], 0.0f), w.y, z);
            z = fmaf(fmaxf(o[4 * i4 + 2], 0.0f), w.z, z);
            z = fmaf(fmaxf(o[4 * i4 + 3], 0.0f), w.w, z);
        }
    }
    return fast_sigmoid(z);
}

// ---------------- kernels ----------------

// Transpose edge_attr [E,T,1] -> [T,E] once (coalesced store side).
__global__ void transpose_ea_kernel(const float* __restrict__ ea) {
    int e = blockIdx.x * blockDim.x + threadIdx.x;
    if (e >= EE) return;
    #pragma unroll
    for (int t = 0; t < TT; t++) g_eaT[t * EE + e] = ea[e * TT + t];
}

// Frame 0 prologue: hidden = 0, agg = 0, s = sigmoid(MLP1([x0, 0]))
__global__ void prologue_kernel(const float* __restrict__ x, const WPtrs p) {
    __shared__ Weights W;
    load_weights(&W, p);
    __syncthreads();
    int n = blockIdx.x * blockDim.x + threadIdx.x;
    if (n >= NN) return;
    float h0[HH] = {0.f, 0.f, 0.f, 0.f, 0.f, 0.f, 0.f, 0.f};
    float x0 = x[n * TT * 2 + 0];
    g_s[n] = mlp1(&W, x0, h0);
    g_agg[n] = 0.0f;
    float4 z4 = make_float4(0.f, 0.f, 0.f, 0.f);
    ((float4*)g_hidden)[n * 2 + 0] = z4;
    ((float4*)g_hidden)[n * 2 + 1] = z4;
}

// Per-frame edge scatter: agg[dst] += s[src] * ea
__global__ void edge_kernel(const int* __restrict__ ei, int t) {
    int e = blockIdx.x * blockDim.x + threadIdx.x;
    if (e >= EE) return;
    int src = ei[t * EE + e];
    int dst = ei[(TT + t) * EE + e];
    float m = __ldg(&g_s[src]) * g_eaT[t * EE + e];
    atomicAdd(&g_agg[dst], m);
}

// Per-frame node update (+ fused message-MLP for the next frame)
__global__ void update_kernel(const float* __restrict__ x, float* __restrict__ out,
                              const WPtrs p, int t) {
    __shared__ Weights W;
    load_weights(&W, p);
    __syncthreads();
    int n = blockIdx.x * blockDim.x + threadIdx.x;
    if (n >= NN) return;

    float h[HH];
    {
        float4 h0 = ((const float4*)g_hidden)[n * 2 + 0];
        float4 h1 = ((const float4*)g_hidden)[n * 2 + 1];
        h[0] = h0.x; h[1] = h0.y; h[2] = h0.z; h[3] = h0.w;
        h[4] = h1.x; h[5] = h1.y; h[6] = h1.z; h[7] = h1.w;
    }

    float upd[10];
    upd[0] = x[(n * TT + t) * 2 + 1];
    #pragma unroll
    for (int j = 0; j < HH; j++) upd[1 + j] = h[j];
    upd[9] = g_agg[n];   // AGG_MEAN=0, AGG_VAR=1 -> identity norm

    float hnew[HH];
    mlp2(&W, upd, hnew);

    ((float4*)g_hidden)[n * 2 + 0] = make_float4(hnew[0], hnew[1], hnew[2], hnew[3]);
    ((float4*)g_hidden)[n * 2 + 1] = make_float4(hnew[4], hnew[5], hnew[6], hnew[7]);

    out[t * NN + n] = node_out(&W, hnew);

    if (t < TT - 1) {
        float x0n = x[(n * TT + t + 1) * 2 + 0];
        g_s[n] = mlp1(&W, x0n, hnew);
        g_agg[n] = 0.0f;
    }
}

// ---------------- launch ----------------
extern "C" void kernel_launch(void* const* d_in, const int* in_sizes, int n_in,
                              void* d_out, int out_size) {
    const float* x  = (const float*)d_in[0];
    const int*   ei = (const int*)d_in[1];
    const float* ea = (const float*)d_in[2];
    WPtrs p;
    p.m1w1 = (const float*)d_in[3];  p.m1b1 = (const float*)d_in[4];
    p.m1w2 = (const float*)d_in[5];  p.m1b2 = (const float*)d_in[6];
    p.m1w3 = (const float*)d_in[7];  p.m1b3 = (const float*)d_in[8];
    p.m2w1 = (const float*)d_in[9];  p.m2b1 = (const float*)d_in[10];
    p.m2w2 = (const float*)d_in[11]; p.m2b2 = (const float*)d_in[12];
    p.ow1  = (const float*)d_in[13]; p.ob1  = (const float*)d_in[14];
    p.ow2  = (const float*)d_in[15]; p.ob2  = (const float*)d_in[16];
    float* out = (float*)d_out;

    transpose_ea_kernel<<<(EE + 255) / 256, 256>>>(ea);
    prologue_kernel<<<(NN + 127) / 128, 128>>>(x, p);
    for (int t = 0; t < TT; t++) {
        edge_kernel<<<(EE + 255) / 256, 256>>>(ei, t);
        update_kernel<<<(NN + 127) / 128, 128>>>(x, out, p, t);
    }
}

// round 6
// speedup vs baseline: 1.0141x; 1.0141x over previous
#include <cuda_runtime.h>

#define NN 50000
#define TT 10
#define EE 1000000
#define HH 8

// ---------------- device scratch (no allocations allowed) ----------------
__device__ float g_hidden[NN * HH];   // [N,H] hidden state
__device__ float g_s[NN];             // per-node sigmoid(message MLP) for current frame
__device__ float g_agg[NN];           // per-node aggregated messages
__device__ float g_eaT[TT * EE];      // edge_attr transposed to [T,E]

// ---------------- weights in shared memory ----------------
struct __align__(16) Weights {
    float m1w1[9 * 32];
    float m1b1[32];
    float m1w2[32 * 32];
    float m1b2[32];
    float m1w3[32];
    float m1b3;
    float pad[3];
    float m2w1[10 * 32];
    float m2b1[32];
    float m2w2[32 * 8];
    float m2b2[8];
    float ow1[8 * 16];
    float ob1[16];
    float ow2[16];
    float ob2;
};

struct WPtrs {
    const float *m1w1, *m1b1, *m1w2, *m1b2, *m1w3, *m1b3;
    const float *m2w1, *m2b1, *m2w2, *m2b2;
    const float *ow1, *ob1, *ow2, *ob2;
};

__device__ __forceinline__ void load_weights(Weights* W, const WPtrs p) {
    const int tid = threadIdx.x, nt = blockDim.x;
    for (int i = tid; i < 9 * 32; i += nt)  W->m1w1[i] = p.m1w1[i];
    for (int i = tid; i < 32; i += nt)      W->m1b1[i] = p.m1b1[i];
    for (int i = tid; i < 32 * 32; i += nt) W->m1w2[i] = p.m1w2[i];
    for (int i = tid; i < 32; i += nt)      W->m1b2[i] = p.m1b2[i];
    for (int i = tid; i < 32; i += nt)      W->m1w3[i] = p.m1w3[i];
    for (int i = tid; i < 10 * 32; i += nt) W->m2w1[i] = p.m2w1[i];
    for (int i = tid; i < 32; i += nt)      W->m2b1[i] = p.m2b1[i];
    for (int i = tid; i < 32 * 8; i += nt)  W->m2w2[i] = p.m2w2[i];
    for (int i = tid; i < 8; i += nt)       W->m2b2[i] = p.m2b2[i];
    for (int i = tid; i < 8 * 16; i += nt)  W->ow1[i] = p.ow1[i];
    for (int i = tid; i < 16; i += nt)      W->ob1[i] = p.ob1[i];
    for (int i = tid; i < 16; i += nt)      W->ow2[i] = p.ow2[i];
    if (tid == 0) { W->m1b3 = p.m1b3[0]; W->ob2 = p.ob2[0]; }
}

__device__ __forceinline__ float fast_sigmoid(float z) {
    return 1.0f / (1.0f + __expf(-z));
}

// ===================== 2-thread-per-node split MLPs =====================
// Each node is handled by lanes (2k, 2k+1). `half` = lane&1 selects the
// output slice of each 32-wide layer; activations are exchanged via shfl.

// Message MLP [x0, h(8)] -> 32 -> 32 -> 1 -> sigmoid. Returns s on BOTH threads.
__device__ __forceinline__ float mlp1_half(const Weights* W, int half, float x0,
                                           const float hf[HH]) {
    const int off = half * 16;
    float a[16];
    {
        const float4* wv = (const float4*)(W->m1w1 + off);
        const float4* bv = (const float4*)(W->m1b1 + off);
        #pragma unroll
        for (int j4 = 0; j4 < 4; j4++) {
            float4 w = wv[j4]; float4 b = bv[j4];
            a[4*j4+0] = fmaf(x0, w.x, b.x);
            a[4*j4+1] = fmaf(x0, w.y, b.y);
            a[4*j4+2] = fmaf(x0, w.z, b.z);
            a[4*j4+3] = fmaf(x0, w.w, b.w);
        }
    }
    #pragma unroll
    for (int i = 0; i < HH; i++) {
        float hi = hf[i];
        const float4* wr = (const float4*)(W->m1w1 + (i + 1) * 32 + off);
        #pragma unroll
        for (int j4 = 0; j4 < 4; j4++) {
            float4 w = wr[j4];
            a[4*j4+0] = fmaf(hi, w.x, a[4*j4+0]);
            a[4*j4+1] = fmaf(hi, w.y, a[4*j4+1]);
            a[4*j4+2] = fmaf(hi, w.z, a[4*j4+2]);
            a[4*j4+3] = fmaf(hi, w.w, a[4*j4+3]);
        }
    }
    #pragma unroll
    for (int j = 0; j < 16; j++) a[j] = fmaxf(a[j], 0.0f);

    // exchange -> full 32-vector
    float af[32];
    #pragma unroll
    for (int i = 0; i < 16; i++) {
        float oa = __shfl_xor_sync(0xffffffffu, a[i], 1);
        af[i]      = half ? oa   : a[i];
        af[16 + i] = half ? a[i] : oa;
    }

    float b[16];
    {
        const float4* bv = (const float4*)(W->m1b2 + off);
        #pragma unroll
        for (int j4 = 0; j4 < 4; j4++) {
            float4 bb = bv[j4];
            b[4*j4+0] = bb.x; b[4*j4+1] = bb.y; b[4*j4+2] = bb.z; b[4*j4+3] = bb.w;
        }
    }
    #pragma unroll
    for (int i = 0; i < 32; i++) {
        float ai = af[i];
        const float4* wr = (const float4*)(W->m1w2 + i * 32 + off);
        #pragma unroll
        for (int j4 = 0; j4 < 4; j4++) {
            float4 w = wr[j4];
            b[4*j4+0] = fmaf(ai, w.x, b[4*j4+0]);
            b[4*j4+1] = fmaf(ai, w.y, b[4*j4+1]);
            b[4*j4+2] = fmaf(ai, w.z, b[4*j4+2]);
            b[4*j4+3] = fmaf(ai, w.w, b[4*j4+3]);
        }
    }
    float z = 0.0f;
    {
        const float4* wv = (const float4*)(W->m1w3 + off);
        #pragma unroll
        for (int i4 = 0; i4 < 4; i4++) {
            float4 w = wv[i4];
            z = fmaf(fmaxf(b[4*i4+0], 0.0f), w.x, z);
            z = fmaf(fmaxf(b[4*i4+1], 0.0f), w.y, z);
            z = fmaf(fmaxf(b[4*i4+2], 0.0f), w.z, z);
            z = fmaf(fmaxf(b[4*i4+3], 0.0f), w.w, z);
        }
    }
    z += __shfl_xor_sync(0xffffffffu, z, 1);
    z += W->m1b3;
    return fast_sigmoid(z);
}

// Update MLP [x1,h(8),agg](10) -> 32 -> relu -> 8 -> relu -> tanh.
// On return: hn[4] = this thread's slice (rows half*4..half*4+3),
// hf[8] = full new hidden on BOTH threads.
__device__ __forceinline__ void mlp2_half(const Weights* W, int half,
                                          const float upd[10], float hn[4], float hf[HH]) {
    const int off = half * 16;
    float a[16];
    {
        const float4* bv = (const float4*)(W->m2b1 + off);
        #pragma unroll
        for (int j4 = 0; j4 < 4; j4++) {
            float4 bb = bv[j4];
            a[4*j4+0] = bb.x; a[4*j4+1] = bb.y; a[4*j4+2] = bb.z; a[4*j4+3] = bb.w;
        }
    }
    #pragma unroll
    for (int i = 0; i < 10; i++) {
        float ui = upd[i];
        const float4* wr = (const float4*)(W->m2w1 + i * 32 + off);
        #pragma unroll
        for (int j4 = 0; j4 < 4; j4++) {
            float4 w = wr[j4];
            a[4*j4+0] = fmaf(ui, w.x, a[4*j4+0]);
            a[4*j4+1] = fmaf(ui, w.y, a[4*j4+1]);
            a[4*j4+2] = fmaf(ui, w.z, a[4*j4+2]);
            a[4*j4+3] = fmaf(ui, w.w, a[4*j4+3]);
        }
    }
    #pragma unroll
    for (int j = 0; j < 16; j++) a[j] = fmaxf(a[j], 0.0f);

    float af[32];
    #pragma unroll
    for (int i = 0; i < 16; i++) {
        float oa = __shfl_xor_sync(0xffffffffu, a[i], 1);
        af[i]      = half ? oa   : a[i];
        af[16 + i] = half ? a[i] : oa;
    }

    // second layer: 8 outputs, this thread computes 4 (cols half*4..half*4+3)
    const int off2 = half * 4;
    float b[4];
    {
        const float4* bv = (const float4*)(W->m2b2 + off2);
        float4 bb = bv[0];
        b[0] = bb.x; b[1] = bb.y; b[2] = bb.z; b[3] = bb.w;
    }
    #pragma unroll
    for (int i = 0; i < 32; i++) {
        float ai = af[i];
        const float4* wr = (const float4*)(W->m2w2 + i * 8 + off2);
        float4 w = wr[0];
        b[0] = fmaf(ai, w.x, b[0]); b[1] = fmaf(ai, w.y, b[1]);
        b[2] = fmaf(ai, w.z, b[2]); b[3] = fmaf(ai, w.w, b[3]);
    }
    // Reference: hidden_new = tanh(relu(z2))
    #pragma unroll
    for (int j = 0; j < 4; j++) hn[j] = tanhf(fmaxf(b[j], 0.0f));

    #pragma unroll
    for (int i = 0; i < 4; i++) {
        float oh = __shfl_xor_sync(0xffffffffu, hn[i], 1);
        hf[i]     = half ? oh    : hn[i];
        hf[4 + i] = half ? hn[i] : oh;
    }
}

// Readout hidden(8) -> 16 -> relu -> 1 -> sigmoid. Valid on BOTH threads.
__device__ __forceinline__ float node_out_half(const Weights* W, int half, const float hf[HH]) {
    const int off = half * 8;
    float o[8];
    {
        const float4* bv = (const float4*)(W->ob1 + off);
        float4 b0 = bv[0], b1 = bv[1];
        o[0]=b0.x; o[1]=b0.y; o[2]=b0.z; o[3]=b0.w;
        o[4]=b1.x; o[5]=b1.y; o[6]=b1.z; o[7]=b1.w;
    }
    #pragma unroll
    for (int i = 0; i < HH; i++) {
        float hi = hf[i];
        const float4* wr = (const float4*)(W->ow1 + i * 16 + off);
        float4 w0 = wr[0], w1 = wr[1];
        o[0]=fmaf(hi,w0.x,o[0]); o[1]=fmaf(hi,w0.y,o[1]);
        o[2]=fmaf(hi,w0.z,o[2]); o[3]=fmaf(hi,w0.w,o[3]);
        o[4]=fmaf(hi,w1.x,o[4]); o[5]=fmaf(hi,w1.y,o[5]);
        o[6]=fmaf(hi,w1.z,o[6]); o[7]=fmaf(hi,w1.w,o[7]);
    }
    float z = 0.0f;
    {
        const float4* wv = (const float4*)(W->ow2 + off);
        float4 w0 = wv[0], w1 = wv[1];
        z = fmaf(fmaxf(o[0],0.f), w0.x, z); z = fmaf(fmaxf(o[1],0.f), w0.y, z);
        z = fmaf(fmaxf(o[2],0.f), w0.z, z); z = fmaf(fmaxf(o[3],0.f), w0.w, z);
        z = fmaf(fmaxf(o[4],0.f), w1.x, z); z = fmaf(fmaxf(o[5],0.f), w1.y, z);
        z = fmaf(fmaxf(o[6],0.f), w1.z, z); z = fmaf(fmaxf(o[7],0.f), w1.w, z);
    }
    z += __shfl_xor_sync(0xffffffffu, z, 1);
    z += W->ob2;
    return fast_sigmoid(z);
}

// ---------------- kernels ----------------

// Transpose edge_attr [E,T,1] -> [T,E] once (contiguous 40B read per thread).
__global__ void transpose_ea_kernel(const float* __restrict__ ea) {
    int e = blockIdx.x * blockDim.x + threadIdx.x;
    if (e >= EE) return;
    #pragma unroll
    for (int t = 0; t < TT; t++) g_eaT[t * EE + e] = ea[e * TT + t];
}

// Frame 0 prologue: hidden = 0, agg = 0, s = sigmoid(MLP1([x0, 0]))
__global__ void prologue_kernel(const float* __restrict__ x, const WPtrs p) {
    __shared__ Weights W;
    load_weights(&W, p);
    __syncthreads();
    int gt = blockIdx.x * blockDim.x + threadIdx.x;
    if (gt >= 2 * NN) return;
    int n = gt >> 1, half = gt & 1;
    float h0[HH] = {0.f,0.f,0.f,0.f,0.f,0.f,0.f,0.f};
    float x0 = x[n * TT * 2 + 0];
    float s = mlp1_half(&W, half, x0, h0);
    if (half == 0) { g_s[n] = s; g_agg[n] = 0.0f; }
    ((float4*)g_hidden)[n * 2 + half] = make_float4(0.f, 0.f, 0.f, 0.f);
}

// Per-frame edge scatter: agg[dst] += s[src] * ea ; 4 edges per thread.
__global__ void edge_kernel(const int* __restrict__ ei, int t) {
    int e4 = blockIdx.x * blockDim.x + threadIdx.x;
    if (e4 >= EE / 4) return;
    int4 s4 = ((const int4*)(ei + t * EE))[e4];
    int4 d4 = ((const int4*)(ei + (TT + t) * EE))[e4];
    float4 a4 = ((const float4*)(g_eaT + t * EE))[e4];
    atomicAdd(&g_agg[d4.x], __ldg(&g_s[s4.x]) * a4.x);
    atomicAdd(&g_agg[d4.y], __ldg(&g_s[s4.y]) * a4.y);
    atomicAdd(&g_agg[d4.z], __ldg(&g_s[s4.z]) * a4.z);
    atomicAdd(&g_agg[d4.w], __ldg(&g_s[s4.w]) * a4.w);
}

// Per-frame node update (+ fused message-MLP for next frame), 2 threads/node.
__global__ void update_kernel(const float* __restrict__ x, float* __restrict__ out,
                              const WPtrs p, int t) {
    __shared__ Weights W;
    load_weights(&W, p);
    __syncthreads();
    int gt = blockIdx.x * blockDim.x + threadIdx.x;
    if (gt >= 2 * NN) return;
    int n = gt >> 1, half = gt & 1;

    float h[HH];
    {
        float4 h0 = ((const float4*)g_hidden)[n * 2 + 0];
        float4 h1 = ((const float4*)g_hidden)[n * 2 + 1];
        h[0]=h0.x; h[1]=h0.y; h[2]=h0.z; h[3]=h0.w;
        h[4]=h1.x; h[5]=h1.y; h[6]=h1.z; h[7]=h1.w;
    }

    float upd[10];
    upd[0] = x[(n * TT + t) * 2 + 1];
    #pragma unroll
    for (int j = 0; j < HH; j++) upd[1 + j] = h[j];
    upd[9] = g_agg[n];   // AGG_MEAN=0, AGG_VAR=1 -> identity norm

    float hn[4], hf[HH];
    mlp2_half(&W, half, upd, hn, hf);

    ((float4*)g_hidden)[n * 2 + half] = make_float4(hn[0], hn[1], hn[2], hn[3]);

    float o = node_out_half(&W, half, hf);
    if (half == 0) out[t * NN + n] = o;

    if (t < TT - 1) {
        float x0n = x[(n * TT + t + 1) * 2 + 0];
        float s = mlp1_half(&W, half, x0n, hf);
        if (half == 0) { g_s[n] = s; g_agg[n] = 0.0f; }
    }
}

// ---------------- launch ----------------
extern "C" void kernel_launch(void* const* d_in, const int* in_sizes, int n_in,
                              void* d_out, int out_size) {
    const float* x  = (const float*)d_in[0];
    const int*   ei = (const int*)d_in[1];
    const float* ea = (const float*)d_in[2];
    WPtrs p;
    p.m1w1 = (const float*)d_in[3];  p.m1b1 = (const float*)d_in[4];
    p.m1w2 = (const float*)d_in[5];  p.m1b2 = (const float*)d_in[6];
    p.m1w3 = (const float*)d_in[7];  p.m1b3 = (const float*)d_in[8];
    p.m2w1 = (const float*)d_in[9];  p.m2b1 = (const float*)d_in[10];
    p.m2w2 = (const float*)d_in[11]; p.m2b2 = (const float*)d_in[12];
    p.ow1  = (const float*)d_in[13]; p.ob1  = (const float*)d_in[14];
    p.ow2  = (const float*)d_in[15]; p.ob2  = (const float*)d_in[16];
    float* out = (float*)d_out;

    transpose_ea_kernel<<<(EE + 255) / 256, 256>>>(ea);
    prologue_kernel<<<(2 * NN + 255) / 256, 256>>>(x, p);
    for (int t = 0; t < TT; t++) {
        edge_kernel<<<(EE / 4 + 255) / 256, 256>>>(ei, t);
        update_kernel<<<(2 * NN + 255) / 256, 256>>>(x, out, p, t);
    }
}